// round 12
// baseline (speedup 1.0000x reference)
#include <cuda_runtime.h>
#include <math.h>

#define NB 16
#define NT 2048
#define NF 768
#define NF4 (NF / 4)          // 192
#define EPSV 1e-5f
#define TSPLIT 64
#define TCHUNK (NT / TSPLIT)  // 32
#define NCTA (TSPLIT * NB)    // 1024 total CTAs

// Persistent device state, zero-initialized at module load.
// Invariant: the finalizer CTA restores acc=0, g_ready=0, g_done=0 at the end
// of every launch -> every graph replay starts clean.
__device__ int    g_seq[NB];
__device__ int    g_ready;            // mask preludes: +1 each (16 total)
__device__ int    g_done;             // completion counter (NCTA)
__device__ float4 g_acc1[NB * NF4];   // sum(x)   accumulators (REDG targets)
__device__ float4 g_acc2[NB * NF4];   // sum(x^2) accumulators

// ---------------------------------------------------------------------------
// Single fused kernel. grid = (TSPLIT, NB) = 1024 CTAs x 192 threads.
// __launch_bounds__(192, 7): 7 CTAs/SM x 148 = 1036 >= 1024 -> ALL CTAs
// co-resident, so the g_ready spin can never deadlock.
//   (bx < 16 && b == 0): mask-sum prelude for batch bx -> g_seq, g_ready.
//   all CTAs: stream full 32-row chunk (ts=bx) unmasked; spin for g_ready
//   (passes instantly: mask preludes done ~7us before any stream finishes);
//   boundary chunk subtracts rows [n, t1) (L1-hot re-read); REDG.F32 into
//   the L2-resident accumulators; last CTA through the counter finalizes.
// ---------------------------------------------------------------------------
__global__ void __launch_bounds__(192, 7)
k_all(const float4* __restrict__ x4, const int4* __restrict__ mask4,
      float4* __restrict__ out4) {
    const int bx  = blockIdx.x;        // chunk index ts
    const int b   = blockIdx.y;
    const int tid = threadIdx.x;

    // ---- mask prelude (16 CTAs only; ~2us, long before any spin) ----
    if (bx < NB && b == 0) {
        int s = 0;
        const int4* mp = mask4 + bx * (NT / 4);
        for (int i = tid; i < NT / 4; i += 192) {
            int4 v = mp[i];
            s += v.x + v.y + v.z + v.w;
        }
#pragma unroll
        for (int off = 16; off; off >>= 1)
            s += __shfl_down_sync(0xffffffffu, s, off);
        __shared__ int ws[6];
        if ((tid & 31) == 0) ws[tid >> 5] = s;
        __syncthreads();
        if (tid == 0) {
            int tot = 0;
#pragma unroll
            for (int w = 0; w < 6; w++) tot += ws[w];
            g_seq[bx] = tot;
            __threadfence();             // release g_seq before the flag
            atomicAdd(&g_ready, 1);
        }
        __syncthreads();
    }

    // ---- stream full 32-row chunk, unmasked (R9 loop, untouched) ----
    const int t0 = bx * TCHUNK;
    const float4* p = x4 + ((size_t)b * NT + (size_t)t0) * NF4 + tid;
    float4 s1 = make_float4(0.f, 0.f, 0.f, 0.f);
    float4 s2 = make_float4(0.f, 0.f, 0.f, 0.f);
#pragma unroll 8
    for (int t = 0; t < TCHUNK; t++, p += NF4) {
        float4 v = *p;
        s1.x += v.x; s1.y += v.y; s1.z += v.z; s1.w += v.w;
        s2.x = fmaf(v.x, v.x, s2.x);
        s2.y = fmaf(v.y, v.y, s2.y);
        s2.z = fmaf(v.z, v.z, s2.z);
        s2.w = fmaf(v.w, v.w, s2.w);
    }

    // ---- acquire n (spin passes instantly; deadlock-free: co-resident) ----
    __shared__ int s_n;
    if (tid == 0) {
        while (*(volatile int*)&g_ready < NB) { }
        __threadfence();                 // acquire g_seq
        int smax = 0, sb = 0;
#pragma unroll
        for (int i = 0; i < NB; i++) {
            int v = *(volatile int*)&g_seq[i];
            smax = max(smax, v);
            if (i == b) sb = v;
        }
        // jnp fp32 semantics: divide, multiply by T, round-half-to-even
        const float rel = (float)sb / (float)smax;
        s_n = (int)rintf(rel * (float)NT);
    }
    __syncthreads();
    const int n  = s_n;
    const int t1 = t0 + TCHUNK;

    if (t0 < n) {
        // boundary chunk: subtract rows [n, t1) -- just streamed, L1-hot
        const int ts2 = max(t0, n);      // == n when boundary, == t1 mostly
        const float4* q = x4 + ((size_t)b * NT + (size_t)ts2) * NF4 + tid;
        for (int t = ts2; t < t1; t++, q += NF4) {
            float4 v = *q;
            s1.x -= v.x; s1.y -= v.y; s1.z -= v.z; s1.w -= v.w;
            s2.x = fmaf(-v.x, v.x, s2.x);
            s2.y = fmaf(-v.y, v.y, s2.y);
            s2.z = fmaf(-v.z, v.z, s2.z);
            s2.w = fmaf(-v.w, v.w, s2.w);
        }
        // fire-and-forget float atomics into L2-resident accumulators
        float* a1 = (float*)g_acc1;
        float* a2 = (float*)g_acc2;
        const int fb = b * NF + tid * 4;
        atomicAdd(&a1[fb + 0], s1.x);
        atomicAdd(&a1[fb + 1], s1.y);
        atomicAdd(&a1[fb + 2], s1.z);
        atomicAdd(&a1[fb + 3], s1.w);
        atomicAdd(&a2[fb + 0], s2.x);
        atomicAdd(&a2[fb + 1], s2.y);
        atomicAdd(&a2[fb + 2], s2.z);
        atomicAdd(&a2[fb + 3], s2.w);
    }
    __threadfence();                     // order atomics before the counter

    // ---- completion counter: last CTA finalizes inline ----
    __shared__ int s_last;
    __syncthreads();
    if (tid == 0) {
        int old = atomicAdd(&g_done, 1);
        s_last = (old == NCTA - 1);
    }
    __syncthreads();
    if (!s_last) return;

    __threadfence();                     // acquire all accumulators

    // read g_seq once; iteration j below is exactly batch j
    int sq[NB], smax = 0;
#pragma unroll
    for (int i = 0; i < NB; i++) {
        sq[i] = g_seq[i];
        smax = max(smax, sq[i]);
    }

    const float4 zero4 = make_float4(0.f, 0.f, 0.f, 0.f);
#pragma unroll
    for (int j = 0; j < NB; j++) {       // idx4 = j*192+tid -> b = j, f4 = tid
        const int idx4 = j * NF4 + tid;
        float4 v1 = g_acc1[idx4];
        float4 v2 = g_acc2[idx4];

        const float rel = (float)sq[j] / (float)smax;
        const float fn  = rintf(rel * (float)NT);
        const float inv = 1.0f / fn;
        const float idd = 1.0f / (fn - 1.0f);

        float4 mean, sd;
        mean.x = v1.x * inv; mean.y = v1.y * inv;
        mean.z = v1.z * inv; mean.w = v1.w * inv;
        sd.x = sqrtf((v2.x - mean.x * v1.x) * idd) + EPSV;
        sd.y = sqrtf((v2.y - mean.y * v1.y) * idd) + EPSV;
        sd.z = sqrtf((v2.z - mean.z * v1.z) * idd) + EPSV;
        sd.w = sqrtf((v2.w - mean.w * v1.w) * idd) + EPSV;

        // NOTE: reference adds jax-threefry gauss noise in [1e-5, 9e-5] to
        // mean. Omitted: ~5e-5 normalized rel err (budget 1e-3, verified R1).
        out4[j * (2 * NF4) + tid]       = mean;   // [B,1,2F]: mean | std
        out4[j * (2 * NF4) + NF4 + tid] = sd;

        g_acc1[idx4] = zero4;            // restore clean state for next replay
        g_acc2[idx4] = zero4;
    }
    if (tid == 0) {
        g_done  = 0;
        g_ready = 0;
    }
}

// ---------------------------------------------------------------------------
extern "C" void kernel_launch(void* const* d_in, const int* in_sizes, int n_in,
                              void* d_out, int out_size) {
    const float* x    = (const float*)d_in[0];   // [16,2048,768] f32
    const int*   mask = (const int*)d_in[1];     // [16,2048] i32
    float*       out  = (float*)d_out;           // [16,1,1536] f32

    k_all<<<dim3(TSPLIT, NB), 192>>>((const float4*)x, (const int4*)mask,
                                     (float4*)out);
}

// round 13
// speedup vs baseline: 1.7534x; 1.7534x over previous
#include <cuda_runtime.h>
#include <math.h>

#define NB 16
#define NT 2048
#define NF 768
#define NF4 (NF / 4)          // 192
#define EPSV 1e-5f
#define TSPLIT 64
#define TCHUNK (NT / TSPLIT)  // 32

// Scratch: every slot unconditionally overwritten each launch -> replay-safe.
// TRANSPOSED layout: g_S1[(b*NF4 + f4) * TSPLIT + ts] so that a k_final warp
// (one per (b,f4)) reads consecutive slots with lane index -> coalesced.
__device__ int    g_seq[NB];
__device__ float4 g_S1[NB * NF4 * TSPLIT];
__device__ float4 g_S2[NB * NF4 * TSPLIT];

// ---------------------------------------------------------------------------
// K1 (fused): blockIdx.x < TSPLIT  -> unmasked 32-row chunk partials
//             blockIdx.x == TSPLIT -> mask row-sum for batch b (hidden under
//             the ~10us of streaming done by the other 1024 CTAs).
// grid = (TSPLIT+1, NB) = 1040 CTAs, 192 threads.
// x is loaded with __ldcs (evict-first): the 100MB stream evicts itself from
// L2 instead of evicting the 12.6MB scratch that k_final needs L2-hot.
// ---------------------------------------------------------------------------
__global__ void __launch_bounds__(192)
k_main(const float4* __restrict__ x4, const int4* __restrict__ mask4) {
    const int ts  = blockIdx.x;
    const int b   = blockIdx.y;
    const int tid = threadIdx.x;

    if (ts == TSPLIT) {
        // ---- mask sum for batch b ----
        int s = 0;
        const int4* mp = mask4 + b * (NT / 4);
        for (int i = tid; i < NT / 4; i += 192) {
            int4 v = mp[i];
            s += v.x + v.y + v.z + v.w;
        }
#pragma unroll
        for (int off = 16; off; off >>= 1)
            s += __shfl_down_sync(0xffffffffu, s, off);
        __shared__ int ws[6];
        if ((tid & 31) == 0) ws[tid >> 5] = s;
        __syncthreads();
        if (tid == 0) {
            int tot = 0;
#pragma unroll
            for (int w = 0; w < 6; w++) tot += ws[w];
            g_seq[b] = tot;
        }
        return;
    }

    // ---- unmasked partial over a full 32-row chunk (streaming loads) ----
    const float4* p = x4 + ((size_t)b * NT + (size_t)ts * TCHUNK) * NF4 + tid;
    float4 s1 = make_float4(0.f, 0.f, 0.f, 0.f);
    float4 s2 = make_float4(0.f, 0.f, 0.f, 0.f);
#pragma unroll 8
    for (int t = 0; t < TCHUNK; t++, p += NF4) {
        float4 v = __ldcs(p);            // evict-first: protect scratch in L2
        s1.x += v.x; s1.y += v.y; s1.z += v.z; s1.w += v.w;
        s2.x = fmaf(v.x, v.x, s2.x);
        s2.y = fmaf(v.y, v.y, s2.y);
        s2.z = fmaf(v.z, v.z, s2.z);
        s2.w = fmaf(v.w, v.w, s2.w);
    }
    // transposed slot store (normal eviction priority -> stays in L2)
    const int idx = (b * NF4 + tid) * TSPLIT + ts;
    g_S1[idx] = s1;
    g_S2[idx] = s2;
}

// ---------------------------------------------------------------------------
// K2: one warp per (b, f4). Lanes cover slots (coalesced via transposed
// layout, now L2-hot) + one boundary row each; warp-shfl tree; no smem.
// grid = NB*NF4/8 = 384 CTAs, block = 256 (8 warps).
// ---------------------------------------------------------------------------
__global__ void __launch_bounds__(256)
k_final(const float4* __restrict__ x4, float4* __restrict__ out4) {
    const int gw   = blockIdx.x * 8 + (threadIdx.x >> 5);  // 0..3071 = b*NF4+f4
    const int lane = threadIdx.x & 31;
    const int b    = gw / NF4;
    const int f4   = gw - b * NF4;

    // ---- unconditional coalesced slot loads: ts = lane, lane+32 ----
    const float4* S1 = g_S1 + (size_t)gw * TSPLIT;
    const float4* S2 = g_S2 + (size_t)gw * TSPLIT;
    float4 a0 = S1[lane];
    float4 a1 = S1[lane + 32];
    float4 c0 = S2[lane];
    float4 c1 = S2[lane + 32];

    // ---- n per-thread (16 ints, L2-broadcast; overlaps the loads) ----
    int smax = 0;
#pragma unroll
    for (int i = 0; i < NB; i++) smax = max(smax, g_seq[i]);
    // jnp fp32 semantics: divide, multiply by T, round-half-to-even
    const float rel = (float)g_seq[b] / (float)smax;
    const int   n   = (int)rintf(rel * (float)NT);
    const int   cb  = n / TCHUNK;               // # fully-valid chunks
    const int   tb  = cb * TCHUNK;

    float4 s1 = make_float4(0.f, 0.f, 0.f, 0.f);
    float4 s2 = make_float4(0.f, 0.f, 0.f, 0.f);
    if (lane < cb) {
        s1.x += a0.x; s1.y += a0.y; s1.z += a0.z; s1.w += a0.w;
        s2.x += c0.x; s2.y += c0.y; s2.z += c0.z; s2.w += c0.w;
    }
    if (lane + 32 < cb) {
        s1.x += a1.x; s1.y += a1.y; s1.z += a1.z; s1.w += a1.w;
        s2.x += c1.x; s2.y += c1.y; s2.z += c1.z; s2.w += c1.w;
    }

    // ---- boundary row per lane: r = tb + lane  (n - tb <= 31) ----
    const int r = tb + lane;
    if (r < n) {
        float4 v = x4[((size_t)b * NT + (size_t)r) * NF4 + f4];
        s1.x += v.x; s1.y += v.y; s1.z += v.z; s1.w += v.w;
        s2.x = fmaf(v.x, v.x, s2.x);
        s2.y = fmaf(v.y, v.y, s2.y);
        s2.z = fmaf(v.z, v.z, s2.z);
        s2.w = fmaf(v.w, v.w, s2.w);
    }

    // ---- warp tree reduction (8 floats), no smem / no barrier ----
#pragma unroll
    for (int off = 16; off; off >>= 1) {
        s1.x += __shfl_down_sync(0xffffffffu, s1.x, off);
        s1.y += __shfl_down_sync(0xffffffffu, s1.y, off);
        s1.z += __shfl_down_sync(0xffffffffu, s1.z, off);
        s1.w += __shfl_down_sync(0xffffffffu, s1.w, off);
        s2.x += __shfl_down_sync(0xffffffffu, s2.x, off);
        s2.y += __shfl_down_sync(0xffffffffu, s2.y, off);
        s2.z += __shfl_down_sync(0xffffffffu, s2.z, off);
        s2.w += __shfl_down_sync(0xffffffffu, s2.w, off);
    }

    if (lane == 0) {
        const float fn  = (float)n;
        const float inv = 1.0f / fn;
        const float idd = 1.0f / (fn - 1.0f);

        float4 mean, sd;
        mean.x = s1.x * inv; mean.y = s1.y * inv;
        mean.z = s1.z * inv; mean.w = s1.w * inv;
        sd.x = sqrtf((s2.x - mean.x * s1.x) * idd) + EPSV;
        sd.y = sqrtf((s2.y - mean.y * s1.y) * idd) + EPSV;
        sd.z = sqrtf((s2.z - mean.z * s1.z) * idd) + EPSV;
        sd.w = sqrtf((s2.w - mean.w * s1.w) * idd) + EPSV;

        // NOTE: reference adds jax-threefry gauss noise in [1e-5, 9e-5] to
        // mean. Omitted: ~5e-5 normalized rel err (budget 1e-3, verified R1).
        out4[b * (2 * NF4) + f4]       = mean;   // [B,1,2F]: mean | std
        out4[b * (2 * NF4) + NF4 + f4] = sd;
    }
}

// ---------------------------------------------------------------------------
extern "C" void kernel_launch(void* const* d_in, const int* in_sizes, int n_in,
                              void* d_out, int out_size) {
    const float* x    = (const float*)d_in[0];   // [16,2048,768] f32
    const int*   mask = (const int*)d_in[1];     // [16,2048] i32
    float*       out  = (float*)d_out;           // [16,1,1536] f32

    k_main<<<dim3(TSPLIT + 1, NB), 192>>>((const float4*)x, (const int4*)mask);
    k_final<<<NB * NF4 / 8, 256>>>((const float4*)x, (float4*)out);
}